// round 15
// baseline (speedup 1.0000x reference)
#include <cuda_runtime.h>
#include <cstdint>

// ---------------------------------------------------------------------------
// R15: R11 skeleton (best: 18.91us) + folded layer-0 circuit (proven in
//      R12/R14). Streaming engine untouched: per-warp bulk-copy ring depth 4,
//      2-sample slots (2 x 2688B copies), uniform 1184-warp split,
//      register-resident BN with monotonic-counter global barrier.
// ---------------------------------------------------------------------------

#define NBLK 296
#define THREADS 128

__device__ float g_partial[NBLK * 8];
__device__ unsigned g_bar = 0;

__device__ __forceinline__ uint32_t smem_u32(const void* p) {
    return (uint32_t)__cvta_generic_to_shared(p);
}

__device__ __forceinline__ unsigned long long f2add(unsigned long long a,
                                                    unsigned long long b) {
    unsigned long long r;
    asm("add.rn.f32x2 %0, %1, %2;" : "=l"(r) : "l"(a), "l"(b));
    return r;
}

__device__ __forceinline__ void mbar_wait(uint32_t mb, int ph) {
    asm volatile(
        "{\n\t.reg .pred P;\n"
        "WAIT_%=:\n\t"
        "mbarrier.try_wait.parity.acquire.cta.shared::cta.b64 P, [%0], %1, 0x989680;\n\t"
        "@!P bra WAIT_%=;\n\t}"
        :: "r"(mb), "r"(ph) : "memory");
}

// lane0: arrive with expected tx, then issue up to 2 bulk copies (clip to s1).
__device__ __forceinline__ void issue_chunk_bulk(
    const float* __restrict__ x, int g0, int s1,
    uint32_t bufaddr, uint32_t mb, int lane)
{
    if (lane == 0) {
        const int v0 = (g0 < s1);
        const int v1 = (g0 + 1 < s1);
        const unsigned tx = (unsigned)(v0 + v1) * 2688u;
        asm volatile("mbarrier.arrive.expect_tx.shared.b64 _, [%0], %1;"
                     :: "r"(mb), "r"(tx) : "memory");
        if (v0)
            asm volatile(
                "cp.async.bulk.shared::cta.global.mbarrier::complete_tx::bytes "
                "[%0], [%1], %2, [%3];"
                :: "r"(bufaddr), "l"(x + (size_t)g0 * 784), "r"(2688u), "r"(mb)
                : "memory");
        if (v1)
            asm volatile(
                "cp.async.bulk.shared::cta.global.mbarrier::complete_tx::bytes "
                "[%0], [%1], %2, [%3];"
                :: "r"(bufaddr + 2688u), "l"(x + (size_t)(g0 + 1) * 784),
                   "r"(2688u), "r"(mb)
                : "memory");
    }
}

// ---- circuit helpers --------------------------------------------------------
template <int S>
__device__ __forceinline__ void apply1q(float re[16], float im[16],
                                        const float* g) {
    const float u00r = g[0], u00i = g[1], u01r = g[2], u01i = g[3];
    const float u10r = g[4], u10i = g[5], u11r = g[6], u11i = g[7];
#pragma unroll
    for (int a = 0; a < 16; ++a) {
        if (a & S) continue;
        const int b = a + S;
        const float x0r = re[a], x0i = im[a];
        const float x1r = re[b], x1i = im[b];
        re[a] = u00r * x0r - u00i * x0i + u01r * x1r - u01i * x1i;
        im[a] = u00r * x0i + u00i * x0r + u01r * x1i + u01i * x1r;
        re[b] = u10r * x0r - u10i * x0i + u11r * x1r - u11i * x1i;
        im[b] = u10r * x0i + u10i * x0r + u11r * x1i + u11i * x1r;
    }
}

template <int SC, int ST>
__device__ __forceinline__ void apply_cnot(float re[16], float im[16]) {
#pragma unroll
    for (int a = 0; a < 16; ++a) {
        if ((a & SC) && !(a & ST)) {
            const int b = a + ST;
            float t;
            t = re[a]; re[a] = re[b]; re[b] = t;
            t = im[a]; im[a] = im[b]; im[b] = t;
        }
    }
}

// Full per-sample circuit with layer-0 Rot folded into the RX product state.
// (Correctness proven in R12 and R14: rel_err ~3e-6.)
__device__ __forceinline__ float4 run_circuit(
    const float* __restrict__ pf2, const float sg[12][8],
    const float* __restrict__ enc_w, const float* __restrict__ enc_b,
    const float* __restrict__ cls_w, const float* __restrict__ cls_b)
{
    float z[4];
#pragma unroll
    for (int w = 0; w < 4; ++w) {
        float acc = __ldg(enc_b + w);
#pragma unroll
        for (int f = 0; f < 16; ++f) acc += pf2[f] * __ldg(enc_w + w * 16 + f);
        z[w] = acc;
    }

    float ar[4], ai[4], br[4], bi[4];
#pragma unroll
    for (int w = 0; w < 4; ++w) {
        float s, c;
        __sincosf(0.5f * z[w], &s, &c);
        const float* g = sg[w];
        ar[w] = g[0] * c + g[3] * s;
        ai[w] = g[1] * c - g[2] * s;
        br[w] = g[4] * c + g[7] * s;
        bi[w] = g[5] * c - g[6] * s;
    }

    float p01r[4], p01i[4], p23r[4], p23i[4];
#pragma unroll
    for (int m = 0; m < 4; ++m) {
        const float x0r = (m & 2) ? br[0] : ar[0];
        const float x0i = (m & 2) ? bi[0] : ai[0];
        const float x1r = (m & 1) ? br[1] : ar[1];
        const float x1i = (m & 1) ? bi[1] : ai[1];
        p01r[m] = x0r * x1r - x0i * x1i;
        p01i[m] = x0r * x1i + x0i * x1r;
        const float y0r = (m & 2) ? br[2] : ar[2];
        const float y0i = (m & 2) ? bi[2] : ai[2];
        const float y1r = (m & 1) ? br[3] : ar[3];
        const float y1i = (m & 1) ? bi[3] : ai[3];
        p23r[m] = y0r * y1r - y0i * y1i;
        p23i[m] = y0r * y1i + y0i * y1r;
    }

    float re[16], im[16];
#pragma unroll
    for (int idx = 0; idx < 16; ++idx) {
        const int m01 = idx >> 2, m23 = idx & 3;
        re[idx] = p01r[m01] * p23r[m23] - p01i[m01] * p23i[m23];
        im[idx] = p01r[m01] * p23i[m23] + p01i[m01] * p23r[m23];
    }

    apply_cnot<8, 4>(re, im);
    apply_cnot<4, 2>(re, im);
    apply_cnot<2, 1>(re, im);

#pragma unroll
    for (int layer = 1; layer < 3; ++layer) {
        apply1q<8>(re, im, sg[layer * 4 + 0]);
        apply1q<4>(re, im, sg[layer * 4 + 1]);
        apply1q<2>(re, im, sg[layer * 4 + 2]);
        apply1q<1>(re, im, sg[layer * 4 + 3]);
        apply_cnot<8, 4>(re, im);
        apply_cnot<4, 2>(re, im);
        apply_cnot<2, 1>(re, im);
    }

    float prob[16];
#pragma unroll
    for (int i = 0; i < 16; ++i) prob[i] = re[i] * re[i] + im[i] * im[i];

    float ev[4];
#pragma unroll
    for (int w = 0; w < 4; ++w) {
        const int s = 8 >> w;
        float e = 0.f;
#pragma unroll
        for (int i = 0; i < 16; ++i) e += (i & s) ? -prob[i] : prob[i];
        ev[w] = e;
    }

    float4 o;
    float* op = &o.x;
#pragma unroll
    for (int oo = 0; oo < 4; ++oo) {
        float acc = __ldg(cls_b + oo);
#pragma unroll
        for (int w = 0; w < 4; ++w) acc += ev[w] * __ldg(cls_w + oo * 4 + w);
        op[oo] = acc;
    }
    return o;
}

// dynamic smem (floats):
//   warp w: 4 slots x 1344 floats (2 samples x 672) at w*5376
//   pooled: [21504, 21504 + 4*28*17)
#define SM_POOLED 21504
#define SMEM_FLOATS (21504 + 4 * 28 * 17)
#define SMEM_BYTES (SMEM_FLOATS * 4)

__global__ __launch_bounds__(THREADS, 2) void qfc_fused(
    const float* __restrict__ x,
    const float* __restrict__ enc_w, const float* __restrict__ enc_b,
    const float* __restrict__ qparams,
    const float* __restrict__ cls_w, const float* __restrict__ cls_b,
    const float* __restrict__ bn_gamma, const float* __restrict__ bn_beta,
    float* __restrict__ out,
    int B, int nwarps, int nblk)
{
    extern __shared__ float smem[];
    float* pooled = smem + SM_POOLED;

    __shared__ float sg[12][8];
    __shared__ float sred[8][8];
    __shared__ float sscale[4], sshift[4];
    __shared__ unsigned long long mbar[16];   // [warp][slot]

    const int tid  = threadIdx.x;
    const int w    = tid >> 5;
    const int lane = tid & 31;

    // --- init: Rot gates + mbarriers ---
    if (tid < 12) {
        const float phi = qparams[tid * 3 + 0];
        const float th  = qparams[tid * 3 + 1];
        const float om  = qparams[tid * 3 + 2];
        float sp, cp, smn, cmn, st, ct;
        sincosf(0.5f * (phi + om), &sp, &cp);
        sincosf(0.5f * (phi - om), &smn, &cmn);
        sincosf(0.5f * th, &st, &ct);
        sg[tid][0] =  ct * cp;   sg[tid][1] = -ct * sp;    // U00
        sg[tid][2] = -st * cmn;  sg[tid][3] = -st * smn;   // U01
        sg[tid][4] =  st * cmn;  sg[tid][5] = -st * smn;   // U10
        sg[tid][6] =  ct * cp;   sg[tid][7] =  ct * sp;    // U11
    }
    if (tid < 16) {
        asm volatile("mbarrier.init.shared.b64 [%0], 1;"
                     :: "r"(smem_u32(&mbar[tid])) : "memory");
    }
    asm volatile("fence.proxy.async.shared::cta;" ::: "memory");
    __syncthreads();

    const uint32_t wbase = smem_u32(smem) + (uint32_t)(w * 5376) * 4u;  // bytes
    const uint32_t mb0   = smem_u32(&mbar[w * 4]);

    // --- this warp's sample range (uniform split over all warps) ---
    const long long Bl = B;
    const int wg = blockIdx.x * 4 + w;
    const int s0 = (int)(Bl * wg / nwarps);
    const int s1 = (int)(Bl * (wg + 1) / nwarps);
    const int ns = s1 - s0;
    const int nch = (ns + 1) >> 1;

    // pooling lane roles (2 samples x 16 features, 6 rows each)
    const int ps  = lane >> 4;
    const int pf  = lane & 15;
    const int ppr = pf >> 2;
    const int ppc = pf & 3;
    const uint32_t poffb = (uint32_t)(ps * 672 + ppr * 168 + ppc * 6) * 4u;
    const bool pcodd = (ppc & 1);

    // --- prologue: fill the 4-slot ring ---
#pragma unroll
    for (int s = 0; s < 4; ++s)
        issue_chunk_bulk(x, s0 + s * 2, s1,
                         wbase + (uint32_t)s * 5376u, mb0 + s * 8, lane);

#pragma unroll 1
    for (int c = 0; c < nch; ++c) {
        const int slot = c & 3;
        const uint32_t bufb = wbase + (uint32_t)slot * 5376u;
        mbar_wait(mb0 + slot * 8, (c >> 2) & 1);

        const int sl = 2 * c + ps;          // local sample index
        if (sl < ns) {
            const uint32_t bp = bufb + poffb;
            unsigned long long acc = 0ull;
            if (pcodd) {
#pragma unroll
                for (int r = 0; r < 6; ++r) {
                    const uint32_t a = bp + r * 112u;
                    unsigned long long p0, p1, p2;
                    asm("ld.shared.b64 %0, [%1];" : "=l"(p0) : "r"(a));
                    asm("ld.shared.v2.b64 {%0, %1}, [%2];"
                        : "=l"(p1), "=l"(p2) : "r"(a + 8u));
                    acc = f2add(acc, f2add(f2add(p0, p1), p2));
                }
            } else {
#pragma unroll
                for (int r = 0; r < 6; ++r) {
                    const uint32_t a = bp + r * 112u;
                    unsigned long long p0, p1, p2;
                    asm("ld.shared.v2.b64 {%0, %1}, [%2];"
                        : "=l"(p0), "=l"(p1) : "r"(a));
                    asm("ld.shared.b64 %0, [%1];" : "=l"(p2) : "r"(a + 16u));
                    acc = f2add(acc, f2add(f2add(p0, p1), p2));
                }
            }
            float lo, hi;
            asm("mov.b64 {%0, %1}, %2;" : "=f"(lo), "=f"(hi) : "l"(acc));
            pooled[(w * 28 + sl) * 17 + pf] = (lo + hi) * (1.0f / 36.0f);
        }
        __syncwarp();

        if (c + 4 < nch)
            issue_chunk_bulk(x, s0 + (c + 4) * 2, s1, bufb, mb0 + slot * 8, lane);
    }
    __syncthreads();   // pooled[] complete across warps (ragged boundaries)

    // --- circuit: one thread per sample of this block ---
    const int ws0 = (int)(Bl * (blockIdx.x * 4 + 0) / nwarps);
    const int ws1 = (int)(Bl * (blockIdx.x * 4 + 1) / nwarps);
    const int ws2 = (int)(Bl * (blockIdx.x * 4 + 2) / nwarps);
    const int ws3 = (int)(Bl * (blockIdx.x * 4 + 3) / nwarps);
    const int wse = (int)(Bl * (blockIdx.x * 4 + 4) / nwarps);

    const int s = ws0 + tid;
    const bool valid = (s < wse);

    float4 o = make_float4(0.f, 0.f, 0.f, 0.f);
    if (valid) {
        int pw, pl;
        if (s >= ws3)      { pw = 3; pl = s - ws3; }
        else if (s >= ws2) { pw = 2; pl = s - ws2; }
        else if (s >= ws1) { pw = 1; pl = s - ws1; }
        else               { pw = 0; pl = s - ws0; }
        const float* pf2 = pooled + (pw * 28 + pl) * 17;
        o = run_circuit(pf2, sg, enc_w, enc_b, cls_w, cls_b);
    }

    // --- per-block BN partials ---
    float acc8[8];
    acc8[0] = o.x;       acc8[1] = o.y;
    acc8[2] = o.z;       acc8[3] = o.w;
    acc8[4] = o.x * o.x; acc8[5] = o.y * o.y;
    acc8[6] = o.z * o.z; acc8[7] = o.w * o.w;
#pragma unroll
    for (int j = 0; j < 8; ++j) {
#pragma unroll
        for (int m = 1; m < 32; m <<= 1)
            acc8[j] += __shfl_xor_sync(0xffffffffu, acc8[j], m);
    }
    if (lane == 0) {
#pragma unroll
        for (int j = 0; j < 8; ++j) sred[w][j] = acc8[j];
    }
    __syncthreads();
    if (tid < 8) {
        float sacc = 0.f;
#pragma unroll
        for (int k = 0; k < 4; ++k) sacc += sred[k][tid];
        g_partial[blockIdx.x * 8 + tid] = sacc;
    }
    __threadfence();
    __syncthreads();

    // --- software global barrier (monotonic counter; graph-replay safe) ---
    if (tid == 0) {
        const unsigned ticket = atomicAdd(&g_bar, 1u);
        const unsigned target = (ticket / (unsigned)nblk + 1u) * (unsigned)nblk;
        while (atomicAdd(&g_bar, 0u) < target) __nanosleep(64);
    }
    __syncthreads();
    __threadfence();

    // --- finalize BN scale/shift (redundant per block; 8-stripe tree) ---
    if (tid < 64) {
        const int j = tid & 7;
        const int g = tid >> 3;
        float sacc = 0.f;
        for (int k = g; k < nblk; k += 8) sacc += g_partial[k * 8 + j];
        sred[g][j] = sacc;
    }
    __syncthreads();
    if (tid < 4) {
        float sum = 0.f, sq = 0.f;
#pragma unroll
        for (int k = 0; k < 8; ++k) { sum += sred[k][tid]; sq += sred[k][tid + 4]; }
        const float invB = 1.0f / (float)B;
        const float mu  = sum * invB;
        const float var = sq * invB - mu * mu;
        const float sc  = bn_gamma[tid] * rsqrtf(var + 1e-5f);
        sscale[tid] = sc;
        sshift[tid] = bn_beta[tid] - mu * sc;
    }
    __syncthreads();

    // --- apply BN straight from registers (single out write per sample) ---
    if (valid) {
        float4 v = o;
        v.x = v.x * sscale[0] + sshift[0];
        v.y = v.y * sscale[1] + sshift[1];
        v.z = v.z * sscale[2] + sshift[2];
        v.w = v.w * sscale[3] + sshift[3];
        reinterpret_cast<float4*>(out)[s] = v;
    }
}

extern "C" void kernel_launch(void* const* d_in, const int* in_sizes, int n_in,
                              void* d_out, int out_size)
{
    const float* x        = (const float*)d_in[0];
    const float* enc_w    = (const float*)d_in[1];
    const float* enc_b    = (const float*)d_in[2];
    const float* qparams  = (const float*)d_in[3];
    const float* cls_w    = (const float*)d_in[4];
    const float* cls_b    = (const float*)d_in[5];
    const float* bn_gamma = (const float*)d_in[6];
    const float* bn_beta  = (const float*)d_in[7];
    float* out = (float*)d_out;

    const int B = in_sizes[0] / 784;
    const int nblk = NBLK;                // exactly 2 blocks per SM
    const int nwarps = nblk * 4;          // 1184 warps, ~27.7 samples each

    cudaFuncSetAttribute(qfc_fused, cudaFuncAttributeMaxDynamicSharedMemorySize,
                         SMEM_BYTES);
    qfc_fused<<<nblk, THREADS, SMEM_BYTES>>>(
        x, enc_w, enc_b, qparams, cls_w, cls_b, bn_gamma, bn_beta, out,
        B, nwarps, nblk);
}

// round 16
// speedup vs baseline: 1.0135x; 1.0135x over previous
#include <cuda_runtime.h>
#include <cstdint>

// ---------------------------------------------------------------------------
// R16: R11 verbatim (best: 18.91us) with ONE change — the global-barrier poll
//      uses ld.acquire.gpu (plain load) instead of atomicAdd(...,0) RMW.
//      Rationale: LTS atomic ALU serializes per-address at ~32cyc/op; ~295
//      polling blocks delayed straggler ARRIVALS behind poll-RMW queues.
//      Loads don't serialize -> barrier cost drops to arrival + L2 latency.
// ---------------------------------------------------------------------------

#define NBLK 296
#define THREADS 128

__device__ float g_partial[NBLK * 8];
__device__ unsigned g_bar = 0;

__device__ __forceinline__ uint32_t smem_u32(const void* p) {
    return (uint32_t)__cvta_generic_to_shared(p);
}

__device__ __forceinline__ unsigned long long f2add(unsigned long long a,
                                                    unsigned long long b) {
    unsigned long long r;
    asm("add.rn.f32x2 %0, %1, %2;" : "=l"(r) : "l"(a), "l"(b));
    return r;
}

__device__ __forceinline__ void mbar_wait(uint32_t mb, int ph) {
    asm volatile(
        "{\n\t.reg .pred P;\n"
        "WAIT_%=:\n\t"
        "mbarrier.try_wait.parity.acquire.cta.shared::cta.b64 P, [%0], %1, 0x989680;\n\t"
        "@!P bra WAIT_%=;\n\t}"
        :: "r"(mb), "r"(ph) : "memory");
}

// lane0: arrive with expected tx, then issue up to 2 bulk copies (clip to s1).
__device__ __forceinline__ void issue_chunk_bulk(
    const float* __restrict__ x, int g0, int s1,
    uint32_t bufaddr, uint32_t mb, int lane)
{
    if (lane == 0) {
        const int v0 = (g0 < s1);
        const int v1 = (g0 + 1 < s1);
        const unsigned tx = (unsigned)(v0 + v1) * 2688u;
        asm volatile("mbarrier.arrive.expect_tx.shared.b64 _, [%0], %1;"
                     :: "r"(mb), "r"(tx) : "memory");
        if (v0)
            asm volatile(
                "cp.async.bulk.shared::cta.global.mbarrier::complete_tx::bytes "
                "[%0], [%1], %2, [%3];"
                :: "r"(bufaddr), "l"(x + (size_t)g0 * 784), "r"(2688u), "r"(mb)
                : "memory");
        if (v1)
            asm volatile(
                "cp.async.bulk.shared::cta.global.mbarrier::complete_tx::bytes "
                "[%0], [%1], %2, [%3];"
                :: "r"(bufaddr + 2688u), "l"(x + (size_t)(g0 + 1) * 784),
                   "r"(2688u), "r"(mb)
                : "memory");
    }
}

// ---- circuit helpers --------------------------------------------------------
template <int S>
__device__ __forceinline__ void apply1q(float re[16], float im[16],
                                        const float* g) {
    const float u00r = g[0], u00i = g[1], u01r = g[2], u01i = g[3];
    const float u10r = g[4], u10i = g[5], u11r = g[6], u11i = g[7];
#pragma unroll
    for (int a = 0; a < 16; ++a) {
        if (a & S) continue;
        const int b = a + S;
        const float x0r = re[a], x0i = im[a];
        const float x1r = re[b], x1i = im[b];
        re[a] = u00r * x0r - u00i * x0i + u01r * x1r - u01i * x1i;
        im[a] = u00r * x0i + u00i * x0r + u01r * x1i + u01i * x1r;
        re[b] = u10r * x0r - u10i * x0i + u11r * x1r - u11i * x1i;
        im[b] = u10r * x0i + u10i * x0r + u11r * x1i + u11i * x1r;
    }
}

template <int SC, int ST>
__device__ __forceinline__ void apply_cnot(float re[16], float im[16]) {
#pragma unroll
    for (int a = 0; a < 16; ++a) {
        if ((a & SC) && !(a & ST)) {
            const int b = a + ST;
            float t;
            t = re[a]; re[a] = re[b]; re[b] = t;
            t = im[a]; im[a] = im[b]; im[b] = t;
        }
    }
}

// Original (unfolded) circuit — measured fastest (R8/R11).
__device__ __forceinline__ float4 run_circuit(
    const float* __restrict__ pf2, const float sg[12][8],
    const float* __restrict__ enc_w, const float* __restrict__ enc_b,
    const float* __restrict__ cls_w, const float* __restrict__ cls_b)
{
    float z[4];
#pragma unroll
    for (int w = 0; w < 4; ++w) {
        float acc = __ldg(enc_b + w);
#pragma unroll
        for (int f = 0; f < 16; ++f) acc += pf2[f] * __ldg(enc_w + w * 16 + f);
        z[w] = acc;
    }

    float cw[4], sw[4];
#pragma unroll
    for (int w = 0; w < 4; ++w) __sincosf(0.5f * z[w], &sw[w], &cw[w]);

    float re[16], im[16];
#pragma unroll
    for (int idx = 0; idx < 16; ++idx) {
        const float p = (idx & 8 ? sw[0] : cw[0]) *
                        (idx & 4 ? sw[1] : cw[1]) *
                        (idx & 2 ? sw[2] : cw[2]) *
                        (idx & 1 ? sw[3] : cw[3]);
        const int m = __popc(idx) & 3;
        re[idx] = (m == 0) ? p : ((m == 2) ? -p : 0.f);
        im[idx] = (m == 1) ? -p : ((m == 3) ? p : 0.f);
    }

#pragma unroll
    for (int layer = 0; layer < 3; ++layer) {
        apply1q<8>(re, im, sg[layer * 4 + 0]);
        apply1q<4>(re, im, sg[layer * 4 + 1]);
        apply1q<2>(re, im, sg[layer * 4 + 2]);
        apply1q<1>(re, im, sg[layer * 4 + 3]);
        apply_cnot<8, 4>(re, im);
        apply_cnot<4, 2>(re, im);
        apply_cnot<2, 1>(re, im);
    }

    float prob[16];
#pragma unroll
    for (int i = 0; i < 16; ++i) prob[i] = re[i] * re[i] + im[i] * im[i];

    float ev[4];
#pragma unroll
    for (int w = 0; w < 4; ++w) {
        const int s = 8 >> w;
        float e = 0.f;
#pragma unroll
        for (int i = 0; i < 16; ++i) e += (i & s) ? -prob[i] : prob[i];
        ev[w] = e;
    }

    float4 o;
    float* op = &o.x;
#pragma unroll
    for (int oo = 0; oo < 4; ++oo) {
        float acc = __ldg(cls_b + oo);
#pragma unroll
        for (int w = 0; w < 4; ++w) acc += ev[w] * __ldg(cls_w + oo * 4 + w);
        op[oo] = acc;
    }
    return o;
}

// dynamic smem (floats):
//   warp w: 4 slots x 1344 floats (2 samples x 672) at w*5376
//   pooled: [21504, 21504 + 4*28*17)
#define SM_POOLED 21504
#define SMEM_FLOATS (21504 + 4 * 28 * 17)
#define SMEM_BYTES (SMEM_FLOATS * 4)

__global__ __launch_bounds__(THREADS, 2) void qfc_fused(
    const float* __restrict__ x,
    const float* __restrict__ enc_w, const float* __restrict__ enc_b,
    const float* __restrict__ qparams,
    const float* __restrict__ cls_w, const float* __restrict__ cls_b,
    const float* __restrict__ bn_gamma, const float* __restrict__ bn_beta,
    float* __restrict__ out,
    int B, int nwarps, int nblk)
{
    extern __shared__ float smem[];
    float* pooled = smem + SM_POOLED;

    __shared__ float sg[12][8];
    __shared__ float sred[8][8];
    __shared__ float sscale[4], sshift[4];
    __shared__ unsigned long long mbar[16];   // [warp][slot]

    const int tid  = threadIdx.x;
    const int w    = tid >> 5;
    const int lane = tid & 31;

    // --- init: Rot gates + mbarriers ---
    if (tid < 12) {
        const float phi = qparams[tid * 3 + 0];
        const float th  = qparams[tid * 3 + 1];
        const float om  = qparams[tid * 3 + 2];
        float sp, cp, smn, cmn, st, ct;
        sincosf(0.5f * (phi + om), &sp, &cp);
        sincosf(0.5f * (phi - om), &smn, &cmn);
        sincosf(0.5f * th, &st, &ct);
        sg[tid][0] =  ct * cp;   sg[tid][1] = -ct * sp;    // U00
        sg[tid][2] = -st * cmn;  sg[tid][3] = -st * smn;   // U01
        sg[tid][4] =  st * cmn;  sg[tid][5] = -st * smn;   // U10
        sg[tid][6] =  ct * cp;   sg[tid][7] =  ct * sp;    // U11
    }
    if (tid < 16) {
        asm volatile("mbarrier.init.shared.b64 [%0], 1;"
                     :: "r"(smem_u32(&mbar[tid])) : "memory");
    }
    asm volatile("fence.proxy.async.shared::cta;" ::: "memory");
    __syncthreads();

    const uint32_t wbase = smem_u32(smem) + (uint32_t)(w * 5376) * 4u;  // bytes
    const uint32_t mb0   = smem_u32(&mbar[w * 4]);

    // --- this warp's sample range (uniform split over all warps) ---
    const long long Bl = B;
    const int wg = blockIdx.x * 4 + w;
    const int s0 = (int)(Bl * wg / nwarps);
    const int s1 = (int)(Bl * (wg + 1) / nwarps);
    const int ns = s1 - s0;
    const int nch = (ns + 1) >> 1;

    // pooling lane roles (2 samples x 16 features, 6 rows each)
    const int ps  = lane >> 4;
    const int pf  = lane & 15;
    const int ppr = pf >> 2;
    const int ppc = pf & 3;
    const uint32_t poffb = (uint32_t)(ps * 672 + ppr * 168 + ppc * 6) * 4u;
    const bool pcodd = (ppc & 1);

    // --- prologue: fill the 4-slot ring ---
#pragma unroll
    for (int s = 0; s < 4; ++s)
        issue_chunk_bulk(x, s0 + s * 2, s1,
                         wbase + (uint32_t)s * 5376u, mb0 + s * 8, lane);

#pragma unroll 1
    for (int c = 0; c < nch; ++c) {
        const int slot = c & 3;
        const uint32_t bufb = wbase + (uint32_t)slot * 5376u;
        mbar_wait(mb0 + slot * 8, (c >> 2) & 1);

        const int sl = 2 * c + ps;          // local sample index
        if (sl < ns) {
            const uint32_t bp = bufb + poffb;
            unsigned long long acc = 0ull;
            if (pcodd) {
#pragma unroll
                for (int r = 0; r < 6; ++r) {
                    const uint32_t a = bp + r * 112u;
                    unsigned long long p0, p1, p2;
                    asm("ld.shared.b64 %0, [%1];" : "=l"(p0) : "r"(a));
                    asm("ld.shared.v2.b64 {%0, %1}, [%2];"
                        : "=l"(p1), "=l"(p2) : "r"(a + 8u));
                    acc = f2add(acc, f2add(f2add(p0, p1), p2));
                }
            } else {
#pragma unroll
                for (int r = 0; r < 6; ++r) {
                    const uint32_t a = bp + r * 112u;
                    unsigned long long p0, p1, p2;
                    asm("ld.shared.v2.b64 {%0, %1}, [%2];"
                        : "=l"(p0), "=l"(p1) : "r"(a));
                    asm("ld.shared.b64 %0, [%1];" : "=l"(p2) : "r"(a + 16u));
                    acc = f2add(acc, f2add(f2add(p0, p1), p2));
                }
            }
            float lo, hi;
            asm("mov.b64 {%0, %1}, %2;" : "=f"(lo), "=f"(hi) : "l"(acc));
            pooled[(w * 28 + sl) * 17 + pf] = (lo + hi) * (1.0f / 36.0f);
        }
        __syncwarp();

        if (c + 4 < nch)
            issue_chunk_bulk(x, s0 + (c + 4) * 2, s1, bufb, mb0 + slot * 8, lane);
    }
    __syncthreads();   // pooled[] complete across warps (ragged boundaries)

    // --- circuit: one thread per sample of this block ---
    const int ws0 = (int)(Bl * (blockIdx.x * 4 + 0) / nwarps);
    const int ws1 = (int)(Bl * (blockIdx.x * 4 + 1) / nwarps);
    const int ws2 = (int)(Bl * (blockIdx.x * 4 + 2) / nwarps);
    const int ws3 = (int)(Bl * (blockIdx.x * 4 + 3) / nwarps);
    const int wse = (int)(Bl * (blockIdx.x * 4 + 4) / nwarps);

    const int s = ws0 + tid;
    const bool valid = (s < wse);

    float4 o = make_float4(0.f, 0.f, 0.f, 0.f);
    if (valid) {
        int pw, pl;
        if (s >= ws3)      { pw = 3; pl = s - ws3; }
        else if (s >= ws2) { pw = 2; pl = s - ws2; }
        else if (s >= ws1) { pw = 1; pl = s - ws1; }
        else               { pw = 0; pl = s - ws0; }
        const float* pf2 = pooled + (pw * 28 + pl) * 17;
        o = run_circuit(pf2, sg, enc_w, enc_b, cls_w, cls_b);
    }

    // --- per-block BN partials ---
    float acc8[8];
    acc8[0] = o.x;       acc8[1] = o.y;
    acc8[2] = o.z;       acc8[3] = o.w;
    acc8[4] = o.x * o.x; acc8[5] = o.y * o.y;
    acc8[6] = o.z * o.z; acc8[7] = o.w * o.w;
#pragma unroll
    for (int j = 0; j < 8; ++j) {
#pragma unroll
        for (int m = 1; m < 32; m <<= 1)
            acc8[j] += __shfl_xor_sync(0xffffffffu, acc8[j], m);
    }
    if (lane == 0) {
#pragma unroll
        for (int j = 0; j < 8; ++j) sred[w][j] = acc8[j];
    }
    __syncthreads();
    if (tid < 8) {
        float sacc = 0.f;
#pragma unroll
        for (int k = 0; k < 4; ++k) sacc += sred[k][tid];
        g_partial[blockIdx.x * 8 + tid] = sacc;
    }
    __threadfence();
    __syncthreads();

    // --- global barrier: arrival = 1 atomic; poll = acquire LOAD (no RMW) ---
    if (tid == 0) {
        const unsigned ticket = atomicAdd(&g_bar, 1u);
        const unsigned target = (ticket / (unsigned)nblk + 1u) * (unsigned)nblk;
        unsigned cur;
        do {
            asm volatile("ld.acquire.gpu.global.b32 %0, [%1];"
                         : "=r"(cur) : "l"(&g_bar) : "memory");
            if (cur >= target) break;
            __nanosleep(64);
        } while (true);
    }
    __syncthreads();
    __threadfence();

    // --- finalize BN scale/shift (redundant per block; 8-stripe tree) ---
    if (tid < 64) {
        const int j = tid & 7;
        const int g = tid >> 3;
        float sacc = 0.f;
        for (int k = g; k < nblk; k += 8) sacc += g_partial[k * 8 + j];
        sred[g][j] = sacc;
    }
    __syncthreads();
    if (tid < 4) {
        float sum = 0.f, sq = 0.f;
#pragma unroll
        for (int k = 0; k < 8; ++k) { sum += sred[k][tid]; sq += sred[k][tid + 4]; }
        const float invB = 1.0f / (float)B;
        const float mu  = sum * invB;
        const float var = sq * invB - mu * mu;
        const float sc  = bn_gamma[tid] * rsqrtf(var + 1e-5f);
        sscale[tid] = sc;
        sshift[tid] = bn_beta[tid] - mu * sc;
    }
    __syncthreads();

    // --- apply BN straight from registers (single out write per sample) ---
    if (valid) {
        float4 v = o;
        v.x = v.x * sscale[0] + sshift[0];
        v.y = v.y * sscale[1] + sshift[1];
        v.z = v.z * sscale[2] + sshift[2];
        v.w = v.w * sscale[3] + sshift[3];
        reinterpret_cast<float4*>(out)[s] = v;
    }
}

extern "C" void kernel_launch(void* const* d_in, const int* in_sizes, int n_in,
                              void* d_out, int out_size)
{
    const float* x        = (const float*)d_in[0];
    const float* enc_w    = (const float*)d_in[1];
    const float* enc_b    = (const float*)d_in[2];
    const float* qparams  = (const float*)d_in[3];
    const float* cls_w    = (const float*)d_in[4];
    const float* cls_b    = (const float*)d_in[5];
    const float* bn_gamma = (const float*)d_in[6];
    const float* bn_beta  = (const float*)d_in[7];
    float* out = (float*)d_out;

    const int B = in_sizes[0] / 784;
    const int nblk = NBLK;                // exactly 2 blocks per SM
    const int nwarps = nblk * 4;          // 1184 warps, ~27.7 samples each

    cudaFuncSetAttribute(qfc_fused, cudaFuncAttributeMaxDynamicSharedMemorySize,
                         SMEM_BYTES);
    qfc_fused<<<nblk, THREADS, SMEM_BYTES>>>(
        x, enc_w, enc_b, qparams, cls_w, cls_b, bn_gamma, bn_beta, out,
        B, nwarps, nblk);
}